// round 10
// baseline (speedup 1.0000x reference)
#include <cuda_runtime.h>
#include <cuda_fp16.h>
#include <cstdint>

#define N_NODES 50000
#define D_IN 128
#define D_OUT 64
#define N_ETYPES 3
#define E_PER_ETYPE 500000
#define P_ETYPE 0.5f
#define CAP 96   // max in-degree per (etype,node); Poisson(10) tail => never hit

// Scratch (no device mallocs allowed).
__device__ int    g_cnt[N_ETYPES * N_NODES];                    // 0.6 MB
__device__ int    g_bins[(size_t)N_ETYPES * N_NODES * CAP];     // 57.6 MB
__device__ uint2  g_feat16[(size_t)N_NODES * (D_IN / 4)];       // 12.8 MB
__device__ uint2  g_h16[(size_t)N_NODES * (D_IN / 4)];          // 12.8 MB
__device__ __half g_Wt16[D_OUT * D_IN];                         // 16 KB, Wt16[j*128+k] = W[k][j]

__device__ __forceinline__ float tanh_fast(float x) {
    float y;
    asm("tanh.approx.f32 %0, %1;" : "=f"(y) : "f"(x));
    return y;
}

__device__ __forceinline__ uint2 pack4(float a, float b, float c, float d) {
    __half2 lo = __floats2half2_rn(a, b);
    __half2 hi = __floats2half2_rn(c, d);
    uint2 u;
    u.x = *reinterpret_cast<unsigned*>(&lo);
    u.y = *reinterpret_cast<unsigned*>(&hi);
    return u;
}

__device__ __forceinline__ float4 unpack4(uint2 u) {
    __half2 lo = *reinterpret_cast<__half2*>(&u.x);
    __half2 hi = *reinterpret_cast<__half2*>(&u.y);
    float2 a = __half22float2(lo);
    float2 c = __half22float2(hi);
    return make_float4(a.x, a.y, c.x, c.y);
}

// Convert feat fp32 -> fp16 cache; also zero g_cnt and build transposed fp16 W.
__global__ void __launch_bounds__(256) convert_kernel(
    const float* __restrict__ feat, const float* __restrict__ W)
{
    const int i = blockIdx.x * blockDim.x + threadIdx.x;
    if (i < N_ETYPES * N_NODES) g_cnt[i] = 0;
    if (i < D_OUT * D_IN) {
        const int j = i >> 7, k = i & 127;          // Wt16[j][k] = W[k][j]
        g_Wt16[i] = __float2half(W[k * D_OUT + j]);
    }
    if (i >= N_NODES * (D_IN / 4)) return;
    const float4 v = reinterpret_cast<const float4*>(feat)[i];
    g_feat16[i] = pack4(v.x, v.y, v.z, v.w);
}

// Pass 1: bin edges by (etype, dst). 4 edges per thread -> 4 independent chains.
__global__ void __launch_bounds__(256) bin_kernel(const int* __restrict__ edge_index)
{
    const int t = blockIdx.x * blockDim.x + threadIdx.x;
    if (t >= N_ETYPES * (E_PER_ETYPE / 4)) return;
    const int e    = t / (E_PER_ETYPE / 4);
    const int idx4 = (t - e * (E_PER_ETYPE / 4)) * 4;

    const int* base = edge_index + (size_t)e * 2 * E_PER_ETYPE;
    const int4 s = *reinterpret_cast<const int4*>(base + idx4);
    const int4 d = *reinterpret_cast<const int4*>(base + E_PER_ETYPE + idx4);

    const int s0 = atomicAdd(&g_cnt[e * N_NODES + d.x], 1);
    const int s1 = atomicAdd(&g_cnt[e * N_NODES + d.y], 1);
    const int s2 = atomicAdd(&g_cnt[e * N_NODES + d.z], 1);
    const int s3 = atomicAdd(&g_cnt[e * N_NODES + d.w], 1);

    if (s0 < CAP) g_bins[((size_t)e * N_NODES + d.x) * CAP + s0] = s.x;
    if (s1 < CAP) g_bins[((size_t)e * N_NODES + d.y) * CAP + s1] = s.y;
    if (s2 < CAP) g_bins[((size_t)e * N_NODES + d.z) * CAP + s2] = s.z;
    if (s3 < CAP) g_bins[((size_t)e * N_NODES + d.w) * CAP + s3] = s.w;
}

// Pass 2: pull gather-mean (fp16 payload, fp32 accum) + tanh + residual(fp32)
// + tanh -> g_h16. One warp per node; 2 independent gather chains.
__global__ void __launch_bounds__(256) gather_kernel(const float* __restrict__ feat)
{
    const int gw   = (blockIdx.x * blockDim.x + threadIdx.x) >> 5;
    const int lane = threadIdx.x & 31;
    if (gw >= N_NODES) return;
    const int n = gw;

    const float4 f = reinterpret_cast<const float4*>(feat)[(size_t)n * (D_IN / 4) + lane];
    float h0 = f.x, h1 = f.y, h2 = f.z, h3 = f.w;

    #pragma unroll
    for (int e = 0; e < N_ETYPES; e++) {
        const int c = g_cnt[e * N_NODES + n];
        const int* bin = g_bins + ((size_t)e * N_NODES + n) * CAP;
        float4 sa = make_float4(0.f, 0.f, 0.f, 0.f);
        float4 sb = make_float4(0.f, 0.f, 0.f, 0.f);
        int i = 0;
        for (; i + 2 <= c; i += 2) {
            const int2 p = *reinterpret_cast<const int2*>(bin + i);
            const float4 va = unpack4(__ldg(&g_feat16[(size_t)p.x * (D_IN / 4) + lane]));
            const float4 vb = unpack4(__ldg(&g_feat16[(size_t)p.y * (D_IN / 4) + lane]));
            sa.x += va.x; sa.y += va.y; sa.z += va.z; sa.w += va.w;
            sb.x += vb.x; sb.y += vb.y; sb.z += vb.z; sb.w += vb.w;
        }
        if (i < c) {
            const float4 va = unpack4(__ldg(&g_feat16[(size_t)bin[i] * (D_IN / 4) + lane]));
            sa.x += va.x; sa.y += va.y; sa.z += va.z; sa.w += va.w;
        }
        const float inv = 1.0f / fmaxf((float)c, 1.0f);
        h0 += P_ETYPE * tanh_fast((sa.x + sb.x) * inv);
        h1 += P_ETYPE * tanh_fast((sa.y + sb.y) * inv);
        h2 += P_ETYPE * tanh_fast((sa.z + sb.z) * inv);
        h3 += P_ETYPE * tanh_fast((sa.w + sb.w) * inv);
    }

    g_h16[(size_t)n * (D_IN / 4) + lane] =
        pack4(tanh_fast(h0), tanh_fast(h1), tanh_fast(h2), tanh_fast(h3));
}

// Pass 3: out = h @ W + b via HMMA (mma.sync m16n8k16, fp16 in / fp32 accum).
// Block = 128 threads / 64 nodes (grid 782 -> 5.3 blocks/SM, smooth tail).
// ALL A fragments prefetched in one independent LDG batch (one latency
// exposure per warp instead of eight). B (Wt16) staged in shared.
__global__ void __launch_bounds__(128) gemm_hmma_kernel(
    const float* __restrict__ bias, float* __restrict__ out)
{
    __shared__ __align__(16) __half sW[D_OUT * D_IN];   // 16 KB

    const int tid = threadIdx.x;
    {
        const uint4* gw  = reinterpret_cast<const uint4*>(g_Wt16);
        uint4*       sw4 = reinterpret_cast<uint4*>(sW);
        #pragma unroll
        for (int i = tid; i < D_OUT * D_IN / 8; i += 128) sw4[i] = __ldg(&gw[i]);
    }

    const int wid = tid >> 5, lid = tid & 31;
    const int g  = lid >> 2;        // group 0..7
    const int tg = lid & 3;         // thread-in-group 0..3

    const int row0 = blockIdx.x * 64 + wid * 16 + g;        // rows row0, row0+8
    const int r0 = min(row0,     N_NODES - 1);
    const int r1 = min(row0 + 8, N_NODES - 1);

    const uint32_t* h32 = reinterpret_cast<const uint32_t*>(g_h16);  // 64 b32 per row
    const uint32_t* hr0 = h32 + (size_t)r0 * 64;
    const uint32_t* hr1 = h32 + (size_t)r1 * 64;

    // Prefetch A fragments for all 8 K-steps: 32 independent LDGs.
    uint32_t A[8][4];
    #pragma unroll
    for (int ks = 0; ks < 8; ks++) {
        A[ks][0] = __ldg(&hr0[ks * 8 + tg]);
        A[ks][1] = __ldg(&hr1[ks * 8 + tg]);
        A[ks][2] = __ldg(&hr0[ks * 8 + tg + 4]);
        A[ks][3] = __ldg(&hr1[ks * 8 + tg + 4]);
    }

    __syncthreads();   // W tile ready
    const uint32_t* w32 = reinterpret_cast<const uint32_t*>(sW);     // sW[n*64 + kb] b32

    float acc[8][4];
    #pragma unroll
    for (int nt = 0; nt < 8; nt++)
        #pragma unroll
        for (int c = 0; c < 4; c++) acc[nt][c] = 0.f;

    #pragma unroll
    for (int ks = 0; ks < 8; ks++) {
        #pragma unroll
        for (int nt = 0; nt < 8; nt++) {
            const int n = nt * 8 + g;
            const uint32_t b0 = w32[n * 64 + ks * 8 + tg];
            const uint32_t b1 = w32[n * 64 + ks * 8 + tg + 4];
            asm volatile(
                "mma.sync.aligned.m16n8k16.row.col.f32.f16.f16.f32 "
                "{%0,%1,%2,%3}, {%4,%5,%6,%7}, {%8,%9}, {%0,%1,%2,%3};"
                : "+f"(acc[nt][0]), "+f"(acc[nt][1]), "+f"(acc[nt][2]), "+f"(acc[nt][3])
                : "r"(A[ks][0]), "r"(A[ks][1]), "r"(A[ks][2]), "r"(A[ks][3]),
                  "r"(b0), "r"(b1));
        }
    }

    // D frag: c0=D[g][2tg], c1=D[g][2tg+1], c2=D[g+8][2tg], c3=D[g+8][2tg+1]
    const bool v0 = (row0     < N_NODES);
    const bool v1 = (row0 + 8 < N_NODES);
    const float2* b2 = reinterpret_cast<const float2*>(bias);
    float2* o2 = reinterpret_cast<float2*>(out);
    #pragma unroll
    for (int nt = 0; nt < 8; nt++) {
        const int col = nt * 8 + tg * 2;
        const float2 bb = __ldg(&b2[col >> 1]);
        if (v0) o2[((size_t)row0 * D_OUT + col) >> 1] =
                    make_float2(acc[nt][0] + bb.x, acc[nt][1] + bb.y);
        if (v1) o2[((size_t)(row0 + 8) * D_OUT + col) >> 1] =
                    make_float2(acc[nt][2] + bb.x, acc[nt][3] + bb.y);
    }
}

extern "C" void kernel_launch(void* const* d_in, const int* in_sizes, int n_in,
                              void* d_out, int out_size)
{
    // Identify inputs by unique element counts (robust to metadata ordering).
    const float* feat = nullptr;
    const float* W    = nullptr;
    const float* b    = nullptr;
    const int*   ei   = nullptr;
    for (int i = 0; i < n_in; i++) {
        switch (in_sizes[i]) {
            case 6400000: feat = (const float*)d_in[i]; break;
            case 8192:    W    = (const float*)d_in[i]; break;
            case 64:      b    = (const float*)d_in[i]; break;
            case 3000000: ei   = (const int*)d_in[i];   break;
            default: break;
        }
    }
    float* out = (float*)d_out;

    convert_kernel<<<(N_NODES * (D_IN / 4) + 255) / 256, 256>>>(feat, W);

    const int groups = N_ETYPES * (E_PER_ETYPE / 4);
    bin_kernel<<<(groups + 255) / 256, 256>>>(ei);

    gather_kernel<<<(N_NODES + 7) / 8, 256>>>(feat);

    gemm_hmma_kernel<<<(N_NODES + 63) / 64, 128>>>(b, out);
}

// round 11
// speedup vs baseline: 1.0947x; 1.0947x over previous
#include <cuda_runtime.h>
#include <cuda_fp16.h>
#include <cstdint>

#define N_NODES 50000
#define D_IN 128
#define D_OUT 64
#define N_ETYPES 3
#define E_PER_ETYPE 500000
#define P_ETYPE 0.5f
#define CAP 96   // max in-degree per (etype,node); Poisson(10) tail => never hit

// Scratch (no device mallocs allowed).
__device__ int    g_cnt[N_ETYPES * N_NODES];                    // 0.6 MB
__device__ int    g_bins[(size_t)N_ETYPES * N_NODES * CAP];     // 57.6 MB
__device__ uint2  g_feat16[(size_t)N_NODES * (D_IN / 4)];       // 12.8 MB
__device__ uint2  g_h16[(size_t)N_NODES * (D_IN / 4)];          // 12.8 MB
__device__ __half g_Wt16[D_OUT * D_IN];                         // 16 KB, Wt16[j*128+k] = W[k][j]

__device__ __forceinline__ float tanh_fast(float x) {
    float y;
    asm("tanh.approx.f32 %0, %1;" : "=f"(y) : "f"(x));
    return y;
}

__device__ __forceinline__ uint2 pack4(float a, float b, float c, float d) {
    __half2 lo = __floats2half2_rn(a, b);
    __half2 hi = __floats2half2_rn(c, d);
    uint2 u;
    u.x = *reinterpret_cast<unsigned*>(&lo);
    u.y = *reinterpret_cast<unsigned*>(&hi);
    return u;
}

__device__ __forceinline__ float4 unpack4(uint2 u) {
    __half2 lo = *reinterpret_cast<__half2*>(&u.x);
    __half2 hi = *reinterpret_cast<__half2*>(&u.y);
    float2 a = __half22float2(lo);
    float2 c = __half22float2(hi);
    return make_float4(a.x, a.y, c.x, c.y);
}

// Convert feat fp32 -> fp16 cache; also zero g_cnt and build transposed fp16 W.
__global__ void __launch_bounds__(256) convert_kernel(
    const float* __restrict__ feat, const float* __restrict__ W)
{
    const int i = blockIdx.x * blockDim.x + threadIdx.x;
    if (i < N_ETYPES * N_NODES) g_cnt[i] = 0;
    if (i < D_OUT * D_IN) {
        const int j = i >> 7, k = i & 127;          // Wt16[j][k] = W[k][j]
        g_Wt16[i] = __float2half(W[k * D_OUT + j]);
    }
    if (i >= N_NODES * (D_IN / 4)) return;
    const float4 v = reinterpret_cast<const float4*>(feat)[i];
    g_feat16[i] = pack4(v.x, v.y, v.z, v.w);
}

// Pass 1: bin edges by (etype, dst). 4 edges per thread -> 4 independent chains.
__global__ void __launch_bounds__(256) bin_kernel(const int* __restrict__ edge_index)
{
    const int t = blockIdx.x * blockDim.x + threadIdx.x;
    if (t >= N_ETYPES * (E_PER_ETYPE / 4)) return;
    const int e    = t / (E_PER_ETYPE / 4);
    const int idx4 = (t - e * (E_PER_ETYPE / 4)) * 4;

    const int* base = edge_index + (size_t)e * 2 * E_PER_ETYPE;
    const int4 s = *reinterpret_cast<const int4*>(base + idx4);
    const int4 d = *reinterpret_cast<const int4*>(base + E_PER_ETYPE + idx4);

    const int s0 = atomicAdd(&g_cnt[e * N_NODES + d.x], 1);
    const int s1 = atomicAdd(&g_cnt[e * N_NODES + d.y], 1);
    const int s2 = atomicAdd(&g_cnt[e * N_NODES + d.z], 1);
    const int s3 = atomicAdd(&g_cnt[e * N_NODES + d.w], 1);

    if (s0 < CAP) g_bins[((size_t)e * N_NODES + d.x) * CAP + s0] = s.x;
    if (s1 < CAP) g_bins[((size_t)e * N_NODES + d.y) * CAP + s1] = s.y;
    if (s2 < CAP) g_bins[((size_t)e * N_NODES + d.z) * CAP + s2] = s.z;
    if (s3 < CAP) g_bins[((size_t)e * N_NODES + d.w) * CAP + s3] = s.w;
}

// Pass 2: pull gather-mean (fp16 payload, fp32 accum) + tanh + residual(fp32)
// + tanh -> g_h16. One warp per node; 2 independent gather chains.
__global__ void __launch_bounds__(256) gather_kernel(const float* __restrict__ feat)
{
    const int gw   = (blockIdx.x * blockDim.x + threadIdx.x) >> 5;
    const int lane = threadIdx.x & 31;
    if (gw >= N_NODES) return;
    const int n = gw;

    const float4 f = reinterpret_cast<const float4*>(feat)[(size_t)n * (D_IN / 4) + lane];
    float h0 = f.x, h1 = f.y, h2 = f.z, h3 = f.w;

    #pragma unroll
    for (int e = 0; e < N_ETYPES; e++) {
        const int c = g_cnt[e * N_NODES + n];
        const int* bin = g_bins + ((size_t)e * N_NODES + n) * CAP;
        float4 sa = make_float4(0.f, 0.f, 0.f, 0.f);
        float4 sb = make_float4(0.f, 0.f, 0.f, 0.f);
        int i = 0;
        for (; i + 2 <= c; i += 2) {
            const int2 p = *reinterpret_cast<const int2*>(bin + i);
            const float4 va = unpack4(__ldg(&g_feat16[(size_t)p.x * (D_IN / 4) + lane]));
            const float4 vb = unpack4(__ldg(&g_feat16[(size_t)p.y * (D_IN / 4) + lane]));
            sa.x += va.x; sa.y += va.y; sa.z += va.z; sa.w += va.w;
            sb.x += vb.x; sb.y += vb.y; sb.z += vb.z; sb.w += vb.w;
        }
        if (i < c) {
            const float4 va = unpack4(__ldg(&g_feat16[(size_t)bin[i] * (D_IN / 4) + lane]));
            sa.x += va.x; sa.y += va.y; sa.z += va.z; sa.w += va.w;
        }
        const float inv = 1.0f / fmaxf((float)c, 1.0f);
        h0 += P_ETYPE * tanh_fast((sa.x + sb.x) * inv);
        h1 += P_ETYPE * tanh_fast((sa.y + sb.y) * inv);
        h2 += P_ETYPE * tanh_fast((sa.z + sb.z) * inv);
        h3 += P_ETYPE * tanh_fast((sa.w + sb.w) * inv);
    }

    g_h16[(size_t)n * (D_IN / 4) + lane] =
        pack4(tanh_fast(h0), tanh_fast(h1), tanh_fast(h2), tanh_fast(h3));
}

// Pass 3: out = h @ W + b via HMMA (mma.sync m16n8k16, fp16 in / fp32 accum).
// Block = 128 threads / 64 nodes. W staged in FRAGMENT ORDER:
//   sWf[(nt*8+ks)*32 + lane] = {b0, b1}  -> every B access is ONE conflict-free
//   LDS.64 (address == lane mod 32). R10's layout was an 8-way bank conflict
//   on every B read (stride 64 words == 0 mod 32 across the g lanes).
__global__ void __launch_bounds__(128) gemm_hmma_kernel(
    const float* __restrict__ bias, float* __restrict__ out)
{
    __shared__ __align__(16) uint2 sWf[8 * 8 * 32];   // 16 KB, fragment-ordered

    const int tid = threadIdx.x;
    const int wid = tid >> 5, lid = tid & 31;

    // Stage W into fragment order. entry i: lane = i&31, ks = (i>>5)&7, nt = i>>8.
    {
        const uint32_t* w32g = reinterpret_cast<const uint32_t*>(g_Wt16);
        #pragma unroll
        for (int i = tid; i < 8 * 8 * 32; i += 128) {
            const int ln = i & 31;
            const int ks = (i >> 5) & 7;
            const int nt = i >> 8;
            const int gg = ln >> 2;
            const int tt = ln & 3;
            const int n  = nt * 8 + gg;
            const uint32_t b0 = __ldg(&w32g[n * 64 + ks * 8 + tt]);
            const uint32_t b1 = __ldg(&w32g[n * 64 + ks * 8 + tt + 4]);
            sWf[i] = make_uint2(b0, b1);
        }
    }

    const int g  = lid >> 2;        // group 0..7
    const int tg = lid & 3;         // thread-in-group 0..3

    const int row0 = blockIdx.x * 64 + wid * 16 + g;        // rows row0, row0+8
    const int r0 = min(row0,     N_NODES - 1);
    const int r1 = min(row0 + 8, N_NODES - 1);

    const uint32_t* h32 = reinterpret_cast<const uint32_t*>(g_h16);  // 64 b32 per row
    const uint32_t* hr0 = h32 + (size_t)r0 * 64;
    const uint32_t* hr1 = h32 + (size_t)r1 * 64;

    // Prefetch A fragments for all 8 K-steps: 32 independent LDGs.
    uint32_t A[8][4];
    #pragma unroll
    for (int ks = 0; ks < 8; ks++) {
        A[ks][0] = __ldg(&hr0[ks * 8 + tg]);
        A[ks][1] = __ldg(&hr1[ks * 8 + tg]);
        A[ks][2] = __ldg(&hr0[ks * 8 + tg + 4]);
        A[ks][3] = __ldg(&hr1[ks * 8 + tg + 4]);
    }

    __syncthreads();   // W fragments ready

    float acc[8][4];
    #pragma unroll
    for (int nt = 0; nt < 8; nt++)
        #pragma unroll
        for (int c = 0; c < 4; c++) acc[nt][c] = 0.f;

    #pragma unroll
    for (int ks = 0; ks < 8; ks++) {
        #pragma unroll
        for (int nt = 0; nt < 8; nt++) {
            const uint2 bb = sWf[(nt * 8 + ks) * 32 + lid];   // conflict-free LDS.64
            asm volatile(
                "mma.sync.aligned.m16n8k16.row.col.f32.f16.f16.f32 "
                "{%0,%1,%2,%3}, {%4,%5,%6,%7}, {%8,%9}, {%0,%1,%2,%3};"
                : "+f"(acc[nt][0]), "+f"(acc[nt][1]), "+f"(acc[nt][2]), "+f"(acc[nt][3])
                : "r"(A[ks][0]), "r"(A[ks][1]), "r"(A[ks][2]), "r"(A[ks][3]),
                  "r"(bb.x), "r"(bb.y));
        }
    }

    // D frag: c0=D[g][2tg], c1=D[g][2tg+1], c2=D[g+8][2tg], c3=D[g+8][2tg+1]
    const bool v0 = (row0     < N_NODES);
    const bool v1 = (row0 + 8 < N_NODES);
    const float2* b2 = reinterpret_cast<const float2*>(bias);
    float2* o2 = reinterpret_cast<float2*>(out);
    #pragma unroll
    for (int nt = 0; nt < 8; nt++) {
        const int col = nt * 8 + tg * 2;
        const float2 bb = __ldg(&b2[col >> 1]);
        if (v0) o2[((size_t)row0 * D_OUT + col) >> 1] =
                    make_float2(acc[nt][0] + bb.x, acc[nt][1] + bb.y);
        if (v1) o2[((size_t)(row0 + 8) * D_OUT + col) >> 1] =
                    make_float2(acc[nt][2] + bb.x, acc[nt][3] + bb.y);
    }
}

extern "C" void kernel_launch(void* const* d_in, const int* in_sizes, int n_in,
                              void* d_out, int out_size)
{
    // Identify inputs by unique element counts (robust to metadata ordering).
    const float* feat = nullptr;
    const float* W    = nullptr;
    const float* b    = nullptr;
    const int*   ei   = nullptr;
    for (int i = 0; i < n_in; i++) {
        switch (in_sizes[i]) {
            case 6400000: feat = (const float*)d_in[i]; break;
            case 8192:    W    = (const float*)d_in[i]; break;
            case 64:      b    = (const float*)d_in[i]; break;
            case 3000000: ei   = (const int*)d_in[i];   break;
            default: break;
        }
    }
    float* out = (float*)d_out;

    convert_kernel<<<(N_NODES * (D_IN / 4) + 255) / 256, 256>>>(feat, W);

    const int groups = N_ETYPES * (E_PER_ETYPE / 4);
    bin_kernel<<<(groups + 255) / 256, 256>>>(ei);

    gather_kernel<<<(N_NODES + 7) / 8, 256>>>(feat);

    gemm_hmma_kernel<<<(N_NODES + 63) / 64, 128>>>(b, out);
}